// round 16
// baseline (speedup 1.0000x reference)
#include <cuda_runtime.h>
#include <cuda_bf16.h>
#include <cstdint>
#include <math.h>

#define Bsz 8
#define Sseq 4096
#define Hdim 1024
#define NHEAD 16
#define HDm 64
#define BSROWS (Bsz * Sseq)          // 32768
#define EPS_ATTN 1e-6f
#define EPS_LN 1e-12f
#define SPLIT 8

// ---------------- scratch (device globals; no allocation allowed) -----------
__device__ float g_hs[(size_t)BSROWS * Hdim];            // hs (f32)
__device__ __nv_bfloat16 g_qb[(size_t)BSROWS * Hdim];    // q bf16
__device__ __nv_bfloat16 g_kb[(size_t)BSROWS * Hdim];    // k bf16
__device__ __nv_bfloat16 g_vb[(size_t)BSROWS * Hdim];    // v bf16
__device__ __nv_bfloat16 g_kvb[Bsz * NHEAD * HDm * HDm]; // kv state bf16
__device__ float g_ksum[Bsz * NHEAD * HDm];              // sum_s k  [bh][d]
__device__ float g_kvp[SPLIT * Bsz * NHEAD * HDm * HDm]; // kv partials
__device__ float g_ksp[SPLIT * Bsz * NHEAD * HDm];       // ksum partials
__device__ __nv_bfloat16 g_xb[(size_t)BSROWS * Hdim];    // x in bf16
__device__ __nv_bfloat16 g_cb[(size_t)BSROWS * Hdim];    // ctx in bf16
__device__ __nv_bfloat16 g_wqkv[3 * Hdim * Hdim];        // Wq|Wk|Wv bf16
__device__ __nv_bfloat16 g_wd[Hdim * Hdim];

// ---------------- PTX helpers -------------------------------------------------
__device__ __forceinline__ uint32_t smem_u32(const void* p) {
    uint32_t a;
    asm("{ .reg .u64 t; cvta.to.shared.u64 t, %1; cvt.u32.u64 %0, t; }" : "=r"(a) : "l"(p));
    return a;
}

__device__ __forceinline__ void ldm_x4(uint32_t& d0, uint32_t& d1, uint32_t& d2,
                                       uint32_t& d3, uint32_t addr) {
    asm volatile("ldmatrix.sync.aligned.m8n8.x4.shared.b16 {%0,%1,%2,%3}, [%4];"
                 : "=r"(d0), "=r"(d1), "=r"(d2), "=r"(d3) : "r"(addr));
}

__device__ __forceinline__ void ldm_x4t(uint32_t& d0, uint32_t& d1, uint32_t& d2,
                                        uint32_t& d3, uint32_t addr) {
    asm volatile("ldmatrix.sync.aligned.m8n8.x4.trans.shared.b16 {%0,%1,%2,%3}, [%4];"
                 : "=r"(d0), "=r"(d1), "=r"(d2), "=r"(d3) : "r"(addr));
}

__device__ __forceinline__ void mma_bf16(float* c, const uint32_t* a, const uint32_t* b) {
    asm volatile(
        "mma.sync.aligned.m16n8k16.row.col.f32.bf16.bf16.f32 "
        "{%0,%1,%2,%3}, {%4,%5,%6,%7}, {%8,%9}, {%0,%1,%2,%3};"
        : "+f"(c[0]), "+f"(c[1]), "+f"(c[2]), "+f"(c[3])
        : "r"(a[0]), "r"(a[1]), "r"(a[2]), "r"(a[3]), "r"(b[0]), "r"(b[1]));
}

__device__ __forceinline__ void cp16(uint32_t dst, const void* src) {
    asm volatile("cp.async.cg.shared.global [%0], [%1], 16;" :: "r"(dst), "l"(src));
}
#define CP_COMMIT() asm volatile("cp.async.commit_group;" ::: "memory")
#define CP_WAIT0()  asm volatile("cp.async.wait_group 0;" ::: "memory")

__device__ __forceinline__ float elu1(float x) {
    return (x > 0.f) ? (x + 1.f) : __expf(x);
}

// ---------------- BF16 tensor-core GEMM (R11 geometry, frozen) ----------------
// actMask: bit per output-select -> apply elu+1.
#define BKb 64
#define LDB 72
#define TILEB (128 * LDB * 2)        // 18432 B
#define STGB  (2 * TILEB)            // 36864 B
#define GSM_TOT (2 * STGB)           // 73728 B

__global__ __launch_bounds__(256, 2)
void gemm_bf16(const __nv_bfloat16* __restrict__ A, const __nv_bfloat16* __restrict__ W,
               const float* __restrict__ b0, const float* __restrict__ b1,
               const float* __restrict__ b2, const float* __restrict__ resid,
               float* __restrict__ Cf,
               __nv_bfloat16* __restrict__ o0, __nv_bfloat16* __restrict__ o1,
               __nv_bfloat16* __restrict__ o2,
               int K, int actMask)
{
    extern __shared__ char smem[];
    const uint32_t smb = smem_u32(smem);

    const int tid  = threadIdx.x;
    const int lane = tid & 31;
    const int wid  = tid >> 5;
    const int wm   = wid & 1;
    const int wn   = wid >> 1;
    const int row0 = blockIdx.y * 128;
    const int col0 = blockIdx.x * 128;

    const int sel = col0 >> 10;
    const int lc0 = col0 & 1023;
    const float* bias = (sel == 0) ? b0 : ((sel == 1) ? b1 : b2);
    __nv_bfloat16* Cb = (sel == 0) ? o0 : ((sel == 1) ? o1 : o2);
    const int act = (actMask >> sel) & 1;

    const int rA = tid >> 3;
    const int kg = (tid & 7) * 8;

    const __nv_bfloat16* Ap0 = A + (size_t)(row0 + rA) * K + kg;
    const __nv_bfloat16* Ap1 = Ap0 + (size_t)32 * K;
    const __nv_bfloat16* Ap2 = Ap0 + (size_t)64 * K;
    const __nv_bfloat16* Ap3 = Ap0 + (size_t)96 * K;
    const __nv_bfloat16* Wp0 = W + (size_t)(col0 + rA) * K + kg;
    const __nv_bfloat16* Wp1 = Wp0 + (size_t)32 * K;
    const __nv_bfloat16* Wp2 = Wp0 + (size_t)64 * K;
    const __nv_bfloat16* Wp3 = Wp0 + (size_t)96 * K;

    const uint32_t st_off = (uint32_t)(rA * LDB + kg) * 2;
    const uint32_t rstep  = (uint32_t)(32 * LDB) * 2;

    const uint32_t a_lane = ((uint32_t)((wm * 64 + (lane & 15)) * LDB + (lane >> 4) * 8)) * 2;
    const uint32_t b_lane = ((uint32_t)((wn * 32 + ((lane >> 4) << 3) + (lane & 7)) * LDB
                                        + ((lane >> 3) & 1) * 8)) * 2;

    float acc[4][4][4] = {};
    const int nt = K / BKb;

    {
        const uint32_t sb = smb;
        cp16(sb + st_off,             Ap0);
        cp16(sb + st_off + rstep,     Ap1);
        cp16(sb + st_off + 2 * rstep, Ap2);
        cp16(sb + st_off + 3 * rstep, Ap3);
        cp16(sb + TILEB + st_off,             Wp0);
        cp16(sb + TILEB + st_off + rstep,     Wp1);
        cp16(sb + TILEB + st_off + 2 * rstep, Wp2);
        cp16(sb + TILEB + st_off + 3 * rstep, Wp3);
        CP_COMMIT();
    }

    for (int kt = 0; kt < nt; kt++) {
        CP_WAIT0();
        __syncthreads();

        if (kt + 1 < nt) {
            const int g = (kt + 1) * BKb;
            const uint32_t sb = smb + ((kt + 1) & 1) * STGB;
            cp16(sb + st_off,             Ap0 + g);
            cp16(sb + st_off + rstep,     Ap1 + g);
            cp16(sb + st_off + 2 * rstep, Ap2 + g);
            cp16(sb + st_off + 3 * rstep, Ap3 + g);
            cp16(sb + TILEB + st_off,             Wp0 + g);
            cp16(sb + TILEB + st_off + rstep,     Wp1 + g);
            cp16(sb + TILEB + st_off + 2 * rstep, Wp2 + g);
            cp16(sb + TILEB + st_off + 3 * rstep, Wp3 + g);
            CP_COMMIT();
        }

        const uint32_t ab = smb + (kt & 1) * STGB + a_lane;
        const uint32_t bb = smb + (kt & 1) * STGB + TILEB + b_lane;

        #pragma unroll
        for (int kk = 0; kk < BKb; kk += 16) {
            uint32_t af[4][4], bf[4][2];
            #pragma unroll
            for (int mf = 0; mf < 4; mf++)
                ldm_x4(af[mf][0], af[mf][1], af[mf][2], af[mf][3],
                       ab + (uint32_t)(mf * 16 * LDB + kk) * 2);
            #pragma unroll
            for (int np = 0; np < 2; np++)
                ldm_x4(bf[np * 2][0], bf[np * 2][1], bf[np * 2 + 1][0], bf[np * 2 + 1][1],
                       bb + (uint32_t)(np * 16 * LDB + kk) * 2);
            #pragma unroll
            for (int mf = 0; mf < 4; mf++)
                #pragma unroll
                for (int nf = 0; nf < 4; nf++)
                    mma_bf16(acc[mf][nf], af[mf], bf[nf]);
        }
    }

    #pragma unroll
    for (int mf = 0; mf < 4; mf++) {
        #pragma unroll
        for (int nf = 0; nf < 4; nf++) {
            const int r   = row0 + wm * 64 + mf * 16 + (lane >> 2);
            const int cgl = lc0 + wn * 32 + nf * 8 + 2 * (lane & 3);
            const float bb0 = bias[cgl], bb1 = bias[cgl + 1];
            #pragma unroll
            for (int half = 0; half < 2; half++) {
                const int rr = r + half * 8;
                float v0 = acc[mf][nf][half * 2 + 0] + bb0;
                float v1 = acc[mf][nf][half * 2 + 1] + bb1;
                if (resid) {
                    const float* rp = resid + (size_t)rr * Hdim + cgl;
                    v0 += rp[0];
                    v1 += rp[1];
                }
                if (act) {
                    v0 = elu1(v0);
                    v1 = elu1(v1);
                }
                if (Cf) {
                    *(float2*)(Cf + (size_t)rr * Hdim + cgl) = make_float2(v0, v1);
                } else {
                    *(__nv_bfloat162*)(Cb + (size_t)rr * Hdim + cgl) =
                        __floats2bfloat162_rn(v0, v1);
                }
            }
        }
    }
}

// ---------------- f32 -> bf16 conversions -------------------------------------
__global__ void __launch_bounds__(256)
conv_bf16(const float* __restrict__ in, __nv_bfloat16* __restrict__ out, int n4)
{
    const int i = blockIdx.x * blockDim.x + threadIdx.x;
    if (i < n4) {
        float4 v = ((const float4*)in)[i];
        __nv_bfloat162 lo = __floats2bfloat162_rn(v.x, v.y);
        __nv_bfloat162 hi = __floats2bfloat162_rn(v.z, v.w);
        uint2 u;
        u.x = *reinterpret_cast<uint32_t*>(&lo);
        u.y = *reinterpret_cast<uint32_t*>(&hi);
        ((uint2*)out)[i] = u;
    }
}

// all 4 weight matrices in one launch
__global__ void __launch_bounds__(256)
conv_w4(const float* __restrict__ Wq, const float* __restrict__ Wk,
        const float* __restrict__ Wv, const float* __restrict__ Wd,
        __nv_bfloat16* __restrict__ wqkv, __nv_bfloat16* __restrict__ wd)
{
    const int n4 = Hdim * Hdim / 4;
    const int nb = n4 / 256;
    const int j  = blockIdx.x / nb;
    const int i  = (blockIdx.x % nb) * 256 + threadIdx.x;
    const float* src = (j == 0) ? Wq : ((j == 1) ? Wk : ((j == 2) ? Wv : Wd));
    __nv_bfloat16* dst = (j < 3) ? (wqkv + (size_t)j * Hdim * Hdim) : wd;
    float4 v = ((const float4*)src)[i];
    __nv_bfloat162 lo = __floats2bfloat162_rn(v.x, v.y);
    __nv_bfloat162 hi = __floats2bfloat162_rn(v.z, v.w);
    uint2 u;
    u.x = *reinterpret_cast<uint32_t*>(&lo);
    u.y = *reinterpret_cast<uint32_t*>(&hi);
    ((uint2*)dst)[i] = u;
}

// ---------------- kv state (frozen) -------------------------------------------
#define KTP 72
#define KVTILE (128 * KTP * 2)
#define KVSTG  (2 * KVTILE)
#define KVSM   (2 * KVSTG)

__global__ __launch_bounds__(256)
void kv_tc(const __nv_bfloat16* __restrict__ k, const __nv_bfloat16* __restrict__ v,
           float* __restrict__ kvp, float* __restrict__ ksp)
{
    extern __shared__ char smem[];
    const uint32_t smb = smem_u32(smem);

    const int bh = blockIdx.x;
    const int sp = blockIdx.y;
    const int b  = bh / NHEAD, h = bh % NHEAD;
    const int tid  = threadIdx.x;
    const int lane = tid & 31;
    const int wid  = tid >> 5;
    const int mi    = wid & 3;
    const int dbase = (wid >> 2) * 32;

    const int rA = tid >> 3;
    const int kg = (tid & 7) * 8;

    const uint32_t sto  = (uint32_t)(rA * KTP + kg) * 2;
    const uint32_t rstp = (uint32_t)(32 * KTP) * 2;

    const uint32_t aoff = (uint32_t)(((lane >> 4) << 3) + (lane & 7)) * KTP * 2
                        + (uint32_t)(16 * mi + (((lane >> 3) & 1) << 3)) * 2;
    const uint32_t boff = (uint32_t)((((lane >> 3) & 1) << 3) + (lane & 7)) * KTP * 2
                        + (uint32_t)(dbase + ((lane >> 4) << 3)) * 2;

    const int s_begin = sp * (Sseq / SPLIT);
    const __nv_bfloat16* kp = k + ((size_t)(b * Sseq + s_begin + rA)) * Hdim + h * HDm + kg;
    const __nv_bfloat16* vp = v + ((size_t)(b * Sseq + s_begin + rA)) * Hdim + h * HDm + kg;

    float acc[4][4] = {};
    float aks[4][4] = {};
    const uint32_t ones[4] = {0x3F803F80u, 0x3F803F80u, 0x3F803F80u, 0x3F803F80u};

    const int NT = Sseq / SPLIT / 128;

    {
        const uint32_t sb = smb;
        #pragma unroll
        for (int j = 0; j < 4; j++) {
            cp16(sb + sto + j * rstp,          kp + (size_t)(32 * j) * Hdim);
            cp16(sb + KVTILE + sto + j * rstp, vp + (size_t)(32 * j) * Hdim);
        }
        CP_COMMIT();
    }

    for (int tile = 0; tile < NT; tile++) {
        CP_WAIT0();
        __syncthreads();

        if (tile + 1 < NT) {
            const uint32_t sb = smb + ((tile + 1) & 1) * KVSTG;
            const size_t g = (size_t)((tile + 1) * 128) * Hdim;
            #pragma unroll
            for (int j = 0; j < 4; j++) {
                cp16(sb + sto + j * rstp,          kp + g + (size_t)(32 * j) * Hdim);
                cp16(sb + KVTILE + sto + j * rstp, vp + g + (size_t)(32 * j) * Hdim);
            }
            CP_COMMIT();
        }

        const uint32_t ksb = smb + (tile & 1) * KVSTG;
        const uint32_t vsb = ksb + KVTILE;

        #pragma unroll
        for (int st = 0; st < 8; st++) {
            const uint32_t srow = (uint32_t)(st * 16) * KTP * 2;
            uint32_t af[4], bf[4][2];
            ldm_x4t(af[0], af[1], af[2], af[3], vsb + srow + aoff);
            #pragma unroll
            for (int np = 0; np < 2; np++)
                ldm_x4t(bf[np * 2][0], bf[np * 2][1], bf[np * 2 + 1][0], bf[np * 2 + 1][1],
                        ksb + srow + boff + (uint32_t)(np * 16) * 2);
            #pragma unroll
            for (int n = 0; n < 4; n++)
                mma_bf16(acc[n], af, bf[n]);
            if (mi == 0) {
                #pragma unroll
                for (int n = 0; n < 4; n++)
                    mma_bf16(aks[n], ones, bf[n]);
            }
        }
        __syncthreads();
    }

    float* kvo = kvp + ((size_t)sp * Bsz * NHEAD + bh) * HDm * HDm;
    #pragma unroll
    for (int n = 0; n < 4; n++) {
        const int d = dbase + 8 * n + 2 * (lane & 3);
        const int m0 = 16 * mi + (lane >> 2);
        *(float2*)(kvo + (m0 + 0) * HDm + d) = make_float2(acc[n][0], acc[n][1]);
        *(float2*)(kvo + (m0 + 8) * HDm + d) = make_float2(acc[n][2], acc[n][3]);
    }

    if (mi == 0 && (lane >> 2) == 0) {
        float* kso = ksp + ((size_t)sp * Bsz * NHEAD + bh) * HDm;
        #pragma unroll
        for (int n = 0; n < 4; n++) {
            const int d = dbase + 8 * n + 2 * lane;
            *(float2*)(kso + d) = make_float2(aks[n][0], aks[n][1]);
        }
    }
}

__global__ void __launch_bounds__(256)
kv_reduce(const float* __restrict__ kvp, const float* __restrict__ ksp,
          __nv_bfloat16* __restrict__ kvb, float* __restrict__ ksum)
{
    const int KVN = Bsz * NHEAD * HDm * HDm;
    const int KSN = Bsz * NHEAD * HDm;
    const int i = blockIdx.x * 256 + threadIdx.x;
    if (i < KVN) {
        float s = 0.f;
        #pragma unroll
        for (int p = 0; p < SPLIT; p++) s += kvp[(size_t)p * KVN + i];
        kvb[i] = __float2bfloat16(s);
    } else if (i < KVN + KSN) {
        const int j = i - KVN;
        float s = 0.f;
        #pragma unroll
        for (int p = 0; p < SPLIT; p++) s += ksp[(size_t)p * KSN + j];
        ksum[j] = s;
    }
}

// ---------------- ctx via tensor cores (frozen) -------------------------------
#define QP 88

__global__ __launch_bounds__(256)
void ctx_tc(const __nv_bfloat16* __restrict__ q, const __nv_bfloat16* __restrict__ kv,
            const float* __restrict__ ksum, __nv_bfloat16* __restrict__ ctx)
{
    __shared__ __nv_bfloat16 KVb[64 * QP];
    __shared__ __nv_bfloat16 qsm[128 * QP];
    __shared__ float kse[64];
    __shared__ float zr[128];

    const int bh = blockIdx.x;
    const int b  = bh / NHEAD, h = bh % NHEAD;
    const int s0 = blockIdx.y * 128;
    const int tid  = threadIdx.x;
    const int lane = tid & 31;
    const int wid  = tid >> 5;

    const uint32_t kvb = smem_u32(KVb);
    const uint32_t qb_ = smem_u32(qsm);

    {
        const uint32_t* kvg = (const uint32_t*)(kv + (size_t)bh * HDm * HDm);
        #pragma unroll
        for (int t = 0; t < 8; t++) {
            const int i = tid + t * 256;
            const int e = i * 2;
            *(uint32_t*)((char*)KVb + ((e >> 6) * QP + (e & 63)) * 2) = kvg[i];
        }
    }
    if (tid < 64) kse[tid] = ksum[bh * HDm + tid] + EPS_ATTN;

    {
        const int trow = tid >> 3;
        const int dgrp = tid & 7;
        const size_t gb = ((size_t)(b * Sseq + s0) + trow) * Hdim + h * HDm + dgrp * 8;
        #pragma unroll
        for (int j = 0; j < 4; j++) {
            uint4 r = *(const uint4*)(q + gb + (size_t)(32 * j) * Hdim);
            *(uint4*)((char*)qsm + ((trow + 32 * j) * QP + dgrp * 8) * 2) = r;
        }
    }
    __syncthreads();

    if (tid < 128) {
        float dot = 0.f;
        #pragma unroll 8
        for (int d = 0; d < HDm; d++)
            dot = fmaf(__bfloat162float(qsm[tid * QP + d]), kse[d], dot);
        zr[tid] = 1.f / dot;
    }
    __syncthreads();

    float acc[8][4] = {};
    const int srow = wid * 16;
    #pragma unroll
    for (int kk = 0; kk < 64; kk += 16) {
        uint32_t af[4], bf[8][2];
        ldm_x4(af[0], af[1], af[2], af[3],
               qb_ + (uint32_t)((srow + (lane & 15)) * QP + kk + (lane >> 4) * 8) * 2);
        #pragma unroll
        for (int np = 0; np < 4; np++)
            ldm_x4(bf[np * 2][0], bf[np * 2][1], bf[np * 2 + 1][0], bf[np * 2 + 1][1],
                   kvb + (uint32_t)((np * 16 + ((lane >> 4) << 3) + (lane & 7)) * QP
                                    + kk + ((lane >> 3) & 1) * 8) * 2);
        #pragma unroll
        for (int n = 0; n < 8; n++)
            mma_bf16(acc[n], af, bf[n]);
    }

    const int r = lane >> 2;
    const int c = 2 * (lane & 3);
    #pragma unroll
    for (int half = 0; half < 2; half++) {
        const int tl = srow + r + half * 8;
        const float z = zr[tl];
        const size_t base = ((size_t)(b * Sseq + s0 + tl)) * Hdim + h * HDm;
        #pragma unroll
        for (int n = 0; n < 8; n++) {
            const int m = 8 * n + c;
            *(__nv_bfloat162*)(ctx + base + m) =
                __floats2bfloat162_rn(acc[n][half * 2 + 0] * z, acc[n][half * 2 + 1] * z);
        }
    }
}

// ---------------- LayerNorm over rows of 1024
__global__ __launch_bounds__(256)
void ln_kernel(const float* __restrict__ hs, const float* __restrict__ gamma,
               const float* __restrict__ beta, float* __restrict__ out)
{
    const int row = blockIdx.x;
    const int tid = threadIdx.x;
    const float4 v = ((const float4*)(hs + (size_t)row * Hdim))[tid];

    float s  = v.x + v.y + v.z + v.w;
    float sq = v.x * v.x + v.y * v.y + v.z * v.z + v.w * v.w;
    #pragma unroll
    for (int o = 16; o > 0; o >>= 1) {
        s  += __shfl_xor_sync(0xFFFFFFFFu, s, o);
        sq += __shfl_xor_sync(0xFFFFFFFFu, sq, o);
    }
    __shared__ float rs[8], rq[8];
    const int wid = tid >> 5, lane = tid & 31;
    if (lane == 0) { rs[wid] = s; rq[wid] = sq; }
    __syncthreads();
    float sum = 0.f, sumq = 0.f;
    #pragma unroll
    for (int i = 0; i < 8; i++) { sum += rs[i]; sumq += rq[i]; }

    const float mu   = sum * (1.f / Hdim);
    const float var  = sumq * (1.f / Hdim) - mu * mu;
    const float rstd = rsqrtf(var + EPS_LN);

    const float4 g4 = ((const float4*)gamma)[tid];
    const float4 b4 = ((const float4*)beta)[tid];
    float4 o;
    o.x = (v.x - mu) * rstd * g4.x + b4.x;
    o.y = (v.y - mu) * rstd * g4.y + b4.y;
    o.z = (v.z - mu) * rstd * g4.z + b4.z;
    o.w = (v.w - mu) * rstd * g4.w + b4.w;
    ((float4*)(out + (size_t)row * Hdim))[tid] = o;
}

// ---------------- launch ----------------------------------------------------
extern "C" void kernel_launch(void* const* d_in, const int* in_sizes, int n_in,
                              void* d_out, int out_size)
{
    const float* x     = (const float*)d_in[0];
    const float* Wq    = (const float*)d_in[2];
    const float* bq    = (const float*)d_in[3];
    const float* Wk    = (const float*)d_in[4];
    const float* bk    = (const float*)d_in[5];
    const float* Wv    = (const float*)d_in[6];
    const float* bv    = (const float*)d_in[7];
    const float* Wd    = (const float*)d_in[8];
    const float* bd    = (const float*)d_in[9];
    const float* gamma = (const float*)d_in[10];
    const float* beta  = (const float*)d_in[11];
    float* out = (float*)d_out;

    float *hs, *ksum, *kvp, *ksp;
    __nv_bfloat16 *qb, *kb, *vb, *xb, *cb, *wqkv, *wdb, *kvb;
    cudaGetSymbolAddress((void**)&hs,   g_hs);
    cudaGetSymbolAddress((void**)&qb,   g_qb);
    cudaGetSymbolAddress((void**)&kb,   g_kb);
    cudaGetSymbolAddress((void**)&vb,   g_vb);
    cudaGetSymbolAddress((void**)&kvb,  g_kvb);
    cudaGetSymbolAddress((void**)&ksum, g_ksum);
    cudaGetSymbolAddress((void**)&kvp,  g_kvp);
    cudaGetSymbolAddress((void**)&ksp,  g_ksp);
    cudaGetSymbolAddress((void**)&xb,   g_xb);
    cudaGetSymbolAddress((void**)&cb,   g_cb);
    cudaGetSymbolAddress((void**)&wqkv, g_wqkv);
    cudaGetSymbolAddress((void**)&wdb,  g_wd);

    cudaFuncSetAttribute(gemm_bf16, cudaFuncAttributeMaxDynamicSharedMemorySize, GSM_TOT);
    cudaFuncSetAttribute(kv_tc,     cudaFuncAttributeMaxDynamicSharedMemorySize, KVSM);

    // side stream + fork/join events (host infra, created once; captured work
    // is identical on every call)
    static cudaStream_t s2 = nullptr;
    static cudaEvent_t evA = nullptr, evB = nullptr;
    if (s2 == nullptr) {
        cudaStreamCreateWithFlags(&s2, cudaStreamNonBlocking);
        cudaEventCreateWithFlags(&evA, cudaEventDisableTiming);
        cudaEventCreateWithFlags(&evB, cudaEventDisableTiming);
    }

    const int xn4 = (int)((size_t)BSROWS * Hdim / 4);
    const int wn4 = Hdim * Hdim / 4;

    // conversions (stream 0)
    conv_bf16<<<xn4 / 256, 256>>>(x, xb, xn4);
    conv_w4<<<4 * (wn4 / 256), 256>>>(Wq, Wk, Wv, Wd, wqkv, wdb);

    // fork: Q-projection on s2 runs concurrently with KV-projection + kv state
    cudaEventRecord(evA, 0);
    cudaStreamWaitEvent(s2, evA, 0);

    // s2: Q projection (+ elu+1), bf16 output
    gemm_bf16<<<dim3(Hdim / 128, BSROWS / 128), 256, GSM_TOT, s2>>>(
        xb, wqkv, bq, bq, bq, nullptr, nullptr, qb, qb, qb, Hdim, 1);

    // stream 0: K|V projection (k gets elu+1 via actMask bit0; v not)
    gemm_bf16<<<dim3(2 * Hdim / 128, BSROWS / 128), 256, GSM_TOT>>>(
        xb, wqkv + (size_t)Hdim * Hdim, bk, bv, bv, nullptr, nullptr,
        kb, vb, vb, Hdim, 1);

    // stream 0: kv state + ksum, then reduce -> bf16 kv
    kv_tc<<<dim3(Bsz * NHEAD, SPLIT), 256, KVSM>>>(kb, vb, kvp, ksp);
    {
        const int n = Bsz * NHEAD * HDm * HDm + Bsz * NHEAD * HDm;
        kv_reduce<<<(n + 255) / 256, 256>>>(kvp, ksp, kvb, ksum);
    }

    // join: ctx needs q (s2) + kv (stream 0)
    cudaEventRecord(evB, s2);
    cudaStreamWaitEvent(0, evB, 0);

    // ctx
    ctx_tc<<<dim3(Bsz * NHEAD, Sseq / 128), 256>>>(qb, kvb, ksum, cb);

    // output projection + bias + residual -> hs (f32)
    gemm_bf16<<<dim3(Hdim / 128, BSROWS / 128), 256, GSM_TOT>>>(
        cb, wdb, bd, bd, bd, x, hs, nullptr, nullptr, nullptr, Hdim, 0);

    // LayerNorm
    ln_kernel<<<BSROWS, 256>>>(hs, gamma, beta, out);
}

// round 17
// speedup vs baseline: 1.0138x; 1.0138x over previous
#include <cuda_runtime.h>
#include <cuda_bf16.h>
#include <cstdint>
#include <math.h>

#define Bsz 8
#define Sseq 4096
#define Hdim 1024
#define NHEAD 16
#define HDm 64
#define BSROWS (Bsz * Sseq)          // 32768
#define EPS_ATTN 1e-6f
#define EPS_LN 1e-12f
#define SPLIT 8

// ---------------- scratch (device globals; no allocation allowed) -----------
__device__ float g_hs[(size_t)BSROWS * Hdim];            // hs (f32)
__device__ __nv_bfloat16 g_qb[(size_t)BSROWS * Hdim];    // q bf16
__device__ __nv_bfloat16 g_kb[(size_t)BSROWS * Hdim];    // k bf16
__device__ __nv_bfloat16 g_vb[(size_t)BSROWS * Hdim];    // v bf16
__device__ __nv_bfloat16 g_kvb[Bsz * NHEAD * HDm * HDm]; // kv state bf16
__device__ float g_ksum[Bsz * NHEAD * HDm];              // sum_s k  [bh][d]
__device__ float g_kvp[SPLIT * Bsz * NHEAD * HDm * HDm]; // kv partials
__device__ float g_ksp[SPLIT * Bsz * NHEAD * HDm];       // ksum partials
__device__ __nv_bfloat16 g_xb[(size_t)BSROWS * Hdim];    // x in bf16
__device__ __nv_bfloat16 g_cb[(size_t)BSROWS * Hdim];    // ctx in bf16
__device__ __nv_bfloat16 g_wqkv[3 * Hdim * Hdim];        // Wq|Wk|Wv bf16
__device__ __nv_bfloat16 g_wd[Hdim * Hdim];

// ---------------- PTX helpers -------------------------------------------------
__device__ __forceinline__ uint32_t smem_u32(const void* p) {
    uint32_t a;
    asm("{ .reg .u64 t; cvta.to.shared.u64 t, %1; cvt.u32.u64 %0, t; }" : "=r"(a) : "l"(p));
    return a;
}

__device__ __forceinline__ void ldm_x4(uint32_t& d0, uint32_t& d1, uint32_t& d2,
                                       uint32_t& d3, uint32_t addr) {
    asm volatile("ldmatrix.sync.aligned.m8n8.x4.shared.b16 {%0,%1,%2,%3}, [%4];"
                 : "=r"(d0), "=r"(d1), "=r"(d2), "=r"(d3) : "r"(addr));
}

__device__ __forceinline__ void ldm_x4t(uint32_t& d0, uint32_t& d1, uint32_t& d2,
                                        uint32_t& d3, uint32_t addr) {
    asm volatile("ldmatrix.sync.aligned.m8n8.x4.trans.shared.b16 {%0,%1,%2,%3}, [%4];"
                 : "=r"(d0), "=r"(d1), "=r"(d2), "=r"(d3) : "r"(addr));
}

__device__ __forceinline__ void mma_bf16(float* c, const uint32_t* a, const uint32_t* b) {
    asm volatile(
        "mma.sync.aligned.m16n8k16.row.col.f32.bf16.bf16.f32 "
        "{%0,%1,%2,%3}, {%4,%5,%6,%7}, {%8,%9}, {%0,%1,%2,%3};"
        : "+f"(c[0]), "+f"(c[1]), "+f"(c[2]), "+f"(c[3])
        : "r"(a[0]), "r"(a[1]), "r"(a[2]), "r"(a[3]), "r"(b[0]), "r"(b[1]));
}

__device__ __forceinline__ void cp16(uint32_t dst, const void* src) {
    asm volatile("cp.async.cg.shared.global [%0], [%1], 16;" :: "r"(dst), "l"(src));
}
#define CP_COMMIT() asm volatile("cp.async.commit_group;" ::: "memory")
#define CP_WAIT0()  asm volatile("cp.async.wait_group 0;" ::: "memory")

__device__ __forceinline__ float elu1(float x) {
    return (x > 0.f) ? (x + 1.f) : __expf(x);
}

// ---------------- BF16 tensor-core GEMM (exact R11/R15 winner, frozen) --------
#define BKb 64
#define LDB 72
#define TILEB (128 * LDB * 2)        // 18432 B
#define STGB  (2 * TILEB)            // 36864 B
#define GSM_TOT (2 * STGB)           // 73728 B

__global__ __launch_bounds__(256, 2)
void gemm_bf16(const __nv_bfloat16* __restrict__ A, const __nv_bfloat16* __restrict__ W,
               const float* __restrict__ b0, const float* __restrict__ b1,
               const float* __restrict__ b2, const float* __restrict__ resid,
               float* __restrict__ Cf,
               __nv_bfloat16* __restrict__ o0, __nv_bfloat16* __restrict__ o1,
               __nv_bfloat16* __restrict__ o2,
               int K, int actQK)
{
    extern __shared__ char smem[];
    const uint32_t smb = smem_u32(smem);

    const int tid  = threadIdx.x;
    const int lane = tid & 31;
    const int wid  = tid >> 5;
    const int wm   = wid & 1;
    const int wn   = wid >> 1;
    const int row0 = blockIdx.y * 128;
    const int col0 = blockIdx.x * 128;

    const int sel = col0 >> 10;
    const int lc0 = col0 & 1023;
    const float* bias = (sel == 0) ? b0 : ((sel == 1) ? b1 : b2);
    __nv_bfloat16* Cb = (sel == 0) ? o0 : ((sel == 1) ? o1 : o2);
    const int act = actQK && (sel < 2);

    const int rA = tid >> 3;
    const int kg = (tid & 7) * 8;

    const __nv_bfloat16* Ap0 = A + (size_t)(row0 + rA) * K + kg;
    const __nv_bfloat16* Ap1 = Ap0 + (size_t)32 * K;
    const __nv_bfloat16* Ap2 = Ap0 + (size_t)64 * K;
    const __nv_bfloat16* Ap3 = Ap0 + (size_t)96 * K;
    const __nv_bfloat16* Wp0 = W + (size_t)(col0 + rA) * K + kg;
    const __nv_bfloat16* Wp1 = Wp0 + (size_t)32 * K;
    const __nv_bfloat16* Wp2 = Wp0 + (size_t)64 * K;
    const __nv_bfloat16* Wp3 = Wp0 + (size_t)96 * K;

    const uint32_t st_off = (uint32_t)(rA * LDB + kg) * 2;
    const uint32_t rstep  = (uint32_t)(32 * LDB) * 2;

    const uint32_t a_lane = ((uint32_t)((wm * 64 + (lane & 15)) * LDB + (lane >> 4) * 8)) * 2;
    const uint32_t b_lane = ((uint32_t)((wn * 32 + ((lane >> 4) << 3) + (lane & 7)) * LDB
                                        + ((lane >> 3) & 1) * 8)) * 2;

    float acc[4][4][4] = {};
    const int nt = K / BKb;

    {
        const uint32_t sb = smb;
        cp16(sb + st_off,             Ap0);
        cp16(sb + st_off + rstep,     Ap1);
        cp16(sb + st_off + 2 * rstep, Ap2);
        cp16(sb + st_off + 3 * rstep, Ap3);
        cp16(sb + TILEB + st_off,             Wp0);
        cp16(sb + TILEB + st_off + rstep,     Wp1);
        cp16(sb + TILEB + st_off + 2 * rstep, Wp2);
        cp16(sb + TILEB + st_off + 3 * rstep, Wp3);
        CP_COMMIT();
    }

    for (int kt = 0; kt < nt; kt++) {
        CP_WAIT0();
        __syncthreads();

        if (kt + 1 < nt) {
            const int g = (kt + 1) * BKb;
            const uint32_t sb = smb + ((kt + 1) & 1) * STGB;
            cp16(sb + st_off,             Ap0 + g);
            cp16(sb + st_off + rstep,     Ap1 + g);
            cp16(sb + st_off + 2 * rstep, Ap2 + g);
            cp16(sb + st_off + 3 * rstep, Ap3 + g);
            cp16(sb + TILEB + st_off,             Wp0 + g);
            cp16(sb + TILEB + st_off + rstep,     Wp1 + g);
            cp16(sb + TILEB + st_off + 2 * rstep, Wp2 + g);
            cp16(sb + TILEB + st_off + 3 * rstep, Wp3 + g);
            CP_COMMIT();
        }

        const uint32_t ab = smb + (kt & 1) * STGB + a_lane;
        const uint32_t bb = smb + (kt & 1) * STGB + TILEB + b_lane;

        #pragma unroll
        for (int kk = 0; kk < BKb; kk += 16) {
            uint32_t af[4][4], bf[4][2];
            #pragma unroll
            for (int mf = 0; mf < 4; mf++)
                ldm_x4(af[mf][0], af[mf][1], af[mf][2], af[mf][3],
                       ab + (uint32_t)(mf * 16 * LDB + kk) * 2);
            #pragma unroll
            for (int np = 0; np < 2; np++)
                ldm_x4(bf[np * 2][0], bf[np * 2][1], bf[np * 2 + 1][0], bf[np * 2 + 1][1],
                       bb + (uint32_t)(np * 16 * LDB + kk) * 2);
            #pragma unroll
            for (int mf = 0; mf < 4; mf++)
                #pragma unroll
                for (int nf = 0; nf < 4; nf++)
                    mma_bf16(acc[mf][nf], af[mf], bf[nf]);
        }
    }

    #pragma unroll
    for (int mf = 0; mf < 4; mf++) {
        #pragma unroll
        for (int nf = 0; nf < 4; nf++) {
            const int r   = row0 + wm * 64 + mf * 16 + (lane >> 2);
            const int cgl = lc0 + wn * 32 + nf * 8 + 2 * (lane & 3);
            const float bb0 = bias[cgl], bb1 = bias[cgl + 1];
            #pragma unroll
            for (int half = 0; half < 2; half++) {
                const int rr = r + half * 8;
                float v0 = acc[mf][nf][half * 2 + 0] + bb0;
                float v1 = acc[mf][nf][half * 2 + 1] + bb1;
                if (resid) {
                    const float* rp = resid + (size_t)rr * Hdim + cgl;
                    v0 += rp[0];
                    v1 += rp[1];
                }
                if (act) {
                    v0 = elu1(v0);
                    v1 = elu1(v1);
                }
                if (Cf) {
                    *(float2*)(Cf + (size_t)rr * Hdim + cgl) = make_float2(v0, v1);
                } else {
                    *(__nv_bfloat162*)(Cb + (size_t)rr * Hdim + cgl) =
                        __floats2bfloat162_rn(v0, v1);
                }
            }
        }
    }
}

// ---------------- f32 -> bf16 conversions -------------------------------------
__global__ void __launch_bounds__(256)
conv_bf16(const float* __restrict__ in, __nv_bfloat16* __restrict__ out, int n4)
{
    const int i = blockIdx.x * blockDim.x + threadIdx.x;
    if (i < n4) {
        float4 v = ((const float4*)in)[i];
        __nv_bfloat162 lo = __floats2bfloat162_rn(v.x, v.y);
        __nv_bfloat162 hi = __floats2bfloat162_rn(v.z, v.w);
        uint2 u;
        u.x = *reinterpret_cast<uint32_t*>(&lo);
        u.y = *reinterpret_cast<uint32_t*>(&hi);
        ((uint2*)out)[i] = u;
    }
}

__global__ void __launch_bounds__(256)
conv_w3(const float* __restrict__ Wq, const float* __restrict__ Wk,
        const float* __restrict__ Wv, __nv_bfloat16* __restrict__ wqkv)
{
    const int n4 = Hdim * Hdim / 4;
    const int nb = n4 / 256;
    const int j  = blockIdx.x / nb;
    const int i  = (blockIdx.x % nb) * 256 + threadIdx.x;
    const float* src = (j == 0) ? Wq : ((j == 1) ? Wk : Wv);
    __nv_bfloat16* dst = wqkv + (size_t)j * Hdim * Hdim;
    float4 v = ((const float4*)src)[i];
    __nv_bfloat162 lo = __floats2bfloat162_rn(v.x, v.y);
    __nv_bfloat162 hi = __floats2bfloat162_rn(v.z, v.w);
    uint2 u;
    u.x = *reinterpret_cast<uint32_t*>(&lo);
    u.y = *reinterpret_cast<uint32_t*>(&hi);
    ((uint2*)dst)[i] = u;
}

// ---------------- kv state (frozen) -------------------------------------------
#define KTP 72
#define KVTILE (128 * KTP * 2)
#define KVSTG  (2 * KVTILE)
#define KVSM   (2 * KVSTG)

__global__ __launch_bounds__(256)
void kv_tc(const __nv_bfloat16* __restrict__ k, const __nv_bfloat16* __restrict__ v,
           float* __restrict__ kvp, float* __restrict__ ksp)
{
    extern __shared__ char smem[];
    const uint32_t smb = smem_u32(smem);

    const int bh = blockIdx.x;
    const int sp = blockIdx.y;
    const int b  = bh / NHEAD, h = bh % NHEAD;
    const int tid  = threadIdx.x;
    const int lane = tid & 31;
    const int wid  = tid >> 5;
    const int mi    = wid & 3;
    const int dbase = (wid >> 2) * 32;

    const int rA = tid >> 3;
    const int kg = (tid & 7) * 8;

    const uint32_t sto  = (uint32_t)(rA * KTP + kg) * 2;
    const uint32_t rstp = (uint32_t)(32 * KTP) * 2;

    const uint32_t aoff = (uint32_t)(((lane >> 4) << 3) + (lane & 7)) * KTP * 2
                        + (uint32_t)(16 * mi + (((lane >> 3) & 1) << 3)) * 2;
    const uint32_t boff = (uint32_t)((((lane >> 3) & 1) << 3) + (lane & 7)) * KTP * 2
                        + (uint32_t)(dbase + ((lane >> 4) << 3)) * 2;

    const int s_begin = sp * (Sseq / SPLIT);
    const __nv_bfloat16* kp = k + ((size_t)(b * Sseq + s_begin + rA)) * Hdim + h * HDm + kg;
    const __nv_bfloat16* vp = v + ((size_t)(b * Sseq + s_begin + rA)) * Hdim + h * HDm + kg;

    float acc[4][4] = {};
    float aks[4][4] = {};
    const uint32_t ones[4] = {0x3F803F80u, 0x3F803F80u, 0x3F803F80u, 0x3F803F80u};

    const int NT = Sseq / SPLIT / 128;

    {
        const uint32_t sb = smb;
        #pragma unroll
        for (int j = 0; j < 4; j++) {
            cp16(sb + sto + j * rstp,          kp + (size_t)(32 * j) * Hdim);
            cp16(sb + KVTILE + sto + j * rstp, vp + (size_t)(32 * j) * Hdim);
        }
        CP_COMMIT();
    }

    for (int tile = 0; tile < NT; tile++) {
        CP_WAIT0();
        __syncthreads();

        if (tile + 1 < NT) {
            const uint32_t sb = smb + ((tile + 1) & 1) * KVSTG;
            const size_t g = (size_t)((tile + 1) * 128) * Hdim;
            #pragma unroll
            for (int j = 0; j < 4; j++) {
                cp16(sb + sto + j * rstp,          kp + g + (size_t)(32 * j) * Hdim);
                cp16(sb + KVTILE + sto + j * rstp, vp + g + (size_t)(32 * j) * Hdim);
            }
            CP_COMMIT();
        }

        const uint32_t ksb = smb + (tile & 1) * KVSTG;
        const uint32_t vsb = ksb + KVTILE;

        #pragma unroll
        for (int st = 0; st < 8; st++) {
            const uint32_t srow = (uint32_t)(st * 16) * KTP * 2;
            uint32_t af[4], bf[4][2];
            ldm_x4t(af[0], af[1], af[2], af[3], vsb + srow + aoff);
            #pragma unroll
            for (int np = 0; np < 2; np++)
                ldm_x4t(bf[np * 2][0], bf[np * 2][1], bf[np * 2 + 1][0], bf[np * 2 + 1][1],
                        ksb + srow + boff + (uint32_t)(np * 16) * 2);
            #pragma unroll
            for (int n = 0; n < 4; n++)
                mma_bf16(acc[n], af, bf[n]);
            if (mi == 0) {
                #pragma unroll
                for (int n = 0; n < 4; n++)
                    mma_bf16(aks[n], ones, bf[n]);
            }
        }
        __syncthreads();
    }

    float* kvo = kvp + ((size_t)sp * Bsz * NHEAD + bh) * HDm * HDm;
    #pragma unroll
    for (int n = 0; n < 4; n++) {
        const int d = dbase + 8 * n + 2 * (lane & 3);
        const int m0 = 16 * mi + (lane >> 2);
        *(float2*)(kvo + (m0 + 0) * HDm + d) = make_float2(acc[n][0], acc[n][1]);
        *(float2*)(kvo + (m0 + 8) * HDm + d) = make_float2(acc[n][2], acc[n][3]);
    }

    if (mi == 0 && (lane >> 2) == 0) {
        float* kso = ksp + ((size_t)sp * Bsz * NHEAD + bh) * HDm;
        #pragma unroll
        for (int n = 0; n < 4; n++) {
            const int d = dbase + 8 * n + 2 * lane;
            *(float2*)(kso + d) = make_float2(aks[n][0], aks[n][1]);
        }
    }
}

__global__ void __launch_bounds__(256)
kv_reduce(const float* __restrict__ kvp, const float* __restrict__ ksp,
          __nv_bfloat16* __restrict__ kvb, float* __restrict__ ksum)
{
    const int KVN = Bsz * NHEAD * HDm * HDm;
    const int KSN = Bsz * NHEAD * HDm;
    const int i = blockIdx.x * 256 + threadIdx.x;
    if (i < KVN) {
        float s = 0.f;
        #pragma unroll
        for (int p = 0; p < SPLIT; p++) s += kvp[(size_t)p * KVN + i];
        kvb[i] = __float2bfloat16(s);
    } else if (i < KVN + KSN) {
        const int j = i - KVN;
        float s = 0.f;
        #pragma unroll
        for (int p = 0; p < SPLIT; p++) s += ksp[(size_t)p * KSN + j];
        ksum[j] = s;
    }
}

// ---------------- ctx via tensor cores (frozen) -------------------------------
#define QP 88

__global__ __launch_bounds__(256)
void ctx_tc(const __nv_bfloat16* __restrict__ q, const __nv_bfloat16* __restrict__ kv,
            const float* __restrict__ ksum, __nv_bfloat16* __restrict__ ctx)
{
    __shared__ __nv_bfloat16 KVb[64 * QP];
    __shared__ __nv_bfloat16 qsm[128 * QP];
    __shared__ float kse[64];
    __shared__ float zr[128];

    const int bh = blockIdx.x;
    const int b  = bh / NHEAD, h = bh % NHEAD;
    const int s0 = blockIdx.y * 128;
    const int tid  = threadIdx.x;
    const int lane = tid & 31;
    const int wid  = tid >> 5;

    const uint32_t kvb = smem_u32(KVb);
    const uint32_t qb_ = smem_u32(qsm);

    {
        const uint32_t* kvg = (const uint32_t*)(kv + (size_t)bh * HDm * HDm);
        #pragma unroll
        for (int t = 0; t < 8; t++) {
            const int i = tid + t * 256;
            const int e = i * 2;
            *(uint32_t*)((char*)KVb + ((e >> 6) * QP + (e & 63)) * 2) = kvg[i];
        }
    }
    if (tid < 64) kse[tid] = ksum[bh * HDm + tid] + EPS_ATTN;

    {
        const int trow = tid >> 3;
        const int dgrp = tid & 7;
        const size_t gb = ((size_t)(b * Sseq + s0) + trow) * Hdim + h * HDm + dgrp * 8;
        #pragma unroll
        for (int j = 0; j < 4; j++) {
            uint4 r = *(const uint4*)(q + gb + (size_t)(32 * j) * Hdim);
            *(uint4*)((char*)qsm + ((trow + 32 * j) * QP + dgrp * 8) * 2) = r;
        }
    }
    __syncthreads();

    if (tid < 128) {
        float dot = 0.f;
        #pragma unroll 8
        for (int d = 0; d < HDm; d++)
            dot = fmaf(__bfloat162float(qsm[tid * QP + d]), kse[d], dot);
        zr[tid] = 1.f / dot;
    }
    __syncthreads();

    float acc[8][4] = {};
    const int srow = wid * 16;
    #pragma unroll
    for (int kk = 0; kk < 64; kk += 16) {
        uint32_t af[4], bf[8][2];
        ldm_x4(af[0], af[1], af[2], af[3],
               qb_ + (uint32_t)((srow + (lane & 15)) * QP + kk + (lane >> 4) * 8) * 2);
        #pragma unroll
        for (int np = 0; np < 4; np++)
            ldm_x4(bf[np * 2][0], bf[np * 2][1], bf[np * 2 + 1][0], bf[np * 2 + 1][1],
                   kvb + (uint32_t)((np * 16 + ((lane >> 4) << 3) + (lane & 7)) * QP
                                    + kk + ((lane >> 3) & 1) * 8) * 2);
        #pragma unroll
        for (int n = 0; n < 8; n++)
            mma_bf16(acc[n], af, bf[n]);
    }

    const int r = lane >> 2;
    const int c = 2 * (lane & 3);
    #pragma unroll
    for (int half = 0; half < 2; half++) {
        const int tl = srow + r + half * 8;
        const float z = zr[tl];
        const size_t base = ((size_t)(b * Sseq + s0 + tl)) * Hdim + h * HDm;
        #pragma unroll
        for (int n = 0; n < 8; n++) {
            const int m = 8 * n + c;
            *(__nv_bfloat162*)(ctx + base + m) =
                __floats2bfloat162_rn(acc[n][half * 2 + 0] * z, acc[n][half * 2 + 1] * z);
        }
    }
}

// ---------------- LayerNorm: 2 rows per CTA (MLP=2), per-row math unchanged ---
__global__ __launch_bounds__(256)
void ln_kernel(const float* __restrict__ hs, const float* __restrict__ gamma,
               const float* __restrict__ beta, float* __restrict__ out)
{
    const int row0 = blockIdx.x * 2;
    const int tid  = threadIdx.x;
    const float4 va = ((const float4*)(hs + (size_t)row0 * Hdim))[tid];
    const float4 vb = ((const float4*)(hs + (size_t)(row0 + 1) * Hdim))[tid];

    float sa = va.x + va.y + va.z + va.w;
    float qa = va.x * va.x + va.y * va.y + va.z * va.z + va.w * va.w;
    float sb = vb.x + vb.y + vb.z + vb.w;
    float qb = vb.x * vb.x + vb.y * vb.y + vb.z * vb.z + vb.w * vb.w;
    #pragma unroll
    for (int o = 16; o > 0; o >>= 1) {
        sa += __shfl_xor_sync(0xFFFFFFFFu, sa, o);
        qa += __shfl_xor_sync(0xFFFFFFFFu, qa, o);
        sb += __shfl_xor_sync(0xFFFFFFFFu, sb, o);
        qb += __shfl_xor_sync(0xFFFFFFFFu, qb, o);
    }
    __shared__ float rs[2][8], rq[2][8];
    const int wid = tid >> 5, lane = tid & 31;
    if (lane == 0) { rs[0][wid] = sa; rq[0][wid] = qa; rs[1][wid] = sb; rq[1][wid] = qb; }
    __syncthreads();
    float suma = 0.f, sumqa = 0.f, sumb = 0.f, sumqb = 0.f;
    #pragma unroll
    for (int i = 0; i < 8; i++) {
        suma += rs[0][i]; sumqa += rq[0][i];
        sumb += rs[1][i]; sumqb += rq[1][i];
    }

    const float mua   = suma * (1.f / Hdim);
    const float vara  = sumqa * (1.f / Hdim) - mua * mua;
    const float rstda = rsqrtf(vara + EPS_LN);
    const float mub   = sumb * (1.f / Hdim);
    const float varb  = sumqb * (1.f / Hdim) - mub * mub;
    const float rstdb = rsqrtf(varb + EPS_LN);

    const float4 g4 = ((const float4*)gamma)[tid];
    const float4 b4 = ((const float4*)beta)[tid];
    float4 oa, ob;
    oa.x = (va.x - mua) * rstda * g4.x + b4.x;
    oa.y = (va.y - mua) * rstda * g4.y + b4.y;
    oa.z = (va.z - mua) * rstda * g4.z + b4.z;
    oa.w = (va.w - mua) * rstda * g4.w + b4.w;
    ob.x = (vb.x - mub) * rstdb * g4.x + b4.x;
    ob.y = (vb.y - mub) * rstdb * g4.y + b4.y;
    ob.z = (vb.z - mub) * rstdb * g4.z + b4.z;
    ob.w = (vb.w - mub) * rstdb * g4.w + b4.w;
    ((float4*)(out + (size_t)row0 * Hdim))[tid] = oa;
    ((float4*)(out + (size_t)(row0 + 1) * Hdim))[tid] = ob;
}

// ---------------- launch ----------------------------------------------------
extern "C" void kernel_launch(void* const* d_in, const int* in_sizes, int n_in,
                              void* d_out, int out_size)
{
    const float* x     = (const float*)d_in[0];
    const float* Wq    = (const float*)d_in[2];
    const float* bq    = (const float*)d_in[3];
    const float* Wk    = (const float*)d_in[4];
    const float* bk    = (const float*)d_in[5];
    const float* Wv    = (const float*)d_in[6];
    const float* bv    = (const float*)d_in[7];
    const float* Wd    = (const float*)d_in[8];
    const float* bd    = (const float*)d_in[9];
    const float* gamma = (const float*)d_in[10];
    const float* beta  = (const float*)d_in[11];
    float* out = (float*)d_out;

    float *hs, *ksum, *kvp, *ksp;
    __nv_bfloat16 *qb, *kb, *vb, *xb, *cb, *wqkv, *wdb, *kvb;
    cudaGetSymbolAddress((void**)&hs,   g_hs);
    cudaGetSymbolAddress((void**)&qb,   g_qb);
    cudaGetSymbolAddress((void**)&kb,   g_kb);
    cudaGetSymbolAddress((void**)&vb,   g_vb);
    cudaGetSymbolAddress((void**)&kvb,  g_kvb);
    cudaGetSymbolAddress((void**)&ksum, g_ksum);
    cudaGetSymbolAddress((void**)&kvp,  g_kvp);
    cudaGetSymbolAddress((void**)&ksp,  g_ksp);
    cudaGetSymbolAddress((void**)&xb,   g_xb);
    cudaGetSymbolAddress((void**)&cb,   g_cb);
    cudaGetSymbolAddress((void**)&wqkv, g_wqkv);
    cudaGetSymbolAddress((void**)&wdb,  g_wd);

    cudaFuncSetAttribute(gemm_bf16, cudaFuncAttributeMaxDynamicSharedMemorySize, GSM_TOT);
    cudaFuncSetAttribute(kv_tc,     cudaFuncAttributeMaxDynamicSharedMemorySize, KVSM);

    const int xn4 = (int)((size_t)BSROWS * Hdim / 4);
    const int wn4 = Hdim * Hdim / 4;

    conv_bf16<<<xn4 / 256, 256>>>(x, xb, xn4);
    conv_w3<<<3 * (wn4 / 256), 256>>>(Wq, Wk, Wv, wqkv);
    conv_bf16<<<wn4 / 256, 256>>>(Wd, wdb, wn4);

    // fused QKV GEMM (+ elu+1 on q,k), bf16 outputs
    gemm_bf16<<<dim3(3 * Hdim / 128, BSROWS / 128), 256, GSM_TOT>>>(
        xb, wqkv, bq, bk, bv, nullptr, nullptr, qb, kb, vb, Hdim, 1);

    // kv state + ksum (split-S x8)
    kv_tc<<<dim3(Bsz * NHEAD, SPLIT), 256, KVSM>>>(kb, vb, kvp, ksp);

    // reduce partials -> bf16 kv + f32 ksum
    {
        const int n = Bsz * NHEAD * HDm * HDm + Bsz * NHEAD * HDm;
        kv_reduce<<<(n + 255) / 256, 256>>>(kvp, ksp, kvb, ksum);
    }

    // ctx
    ctx_tc<<<dim3(Bsz * NHEAD, Sseq / 128), 256>>>(qb, kvb, ksum, cb);

    // output projection + bias + residual -> hs (f32)
    gemm_bf16<<<dim3(Hdim / 128, BSROWS / 128), 256, GSM_TOT>>>(
        cb, wdb, bd, bd, bd, x, hs, nullptr, nullptr, nullptr, Hdim, 0);

    // LayerNorm (2 rows per CTA)
    ln_kernel<<<BSROWS / 2, 256>>>(hs, gamma, beta, out);
}